// round 15
// baseline (speedup 1.0000x reference)
#include <cuda_runtime.h>
#include <cuda_bf16.h>

// Shapes (fixed for this problem)
#define NB 4
#define NQ 512
#define NK 512
#define ND 256
#define NH 256

#define STRIDE 260            // smem row stride (floats): 16B-aligned, bank-friendly

// Scratch: projected queries/keys (B*Q x H) and (B*K x H)
__device__ float g_qh[NB * NQ * NH];
__device__ float g_kh[NB * NK * NH];

__device__ __forceinline__ float tanh_ap(float x) {
    float y;
    asm("tanh.approx.f32 %0, %1;" : "=f"(y) : "f"(x));
    return y;
}

// MUFU-free tanh: Eigen rational P13/Q6 with bit-trick reciprocal + 2 Newton.
// Runs entirely on the FMA/ALU pipes; abs err ~1e-5 on clamped range.
__device__ __forceinline__ float tanh_fma(float x) {
    x = fminf(fmaxf(x, -7.90531110763549805f), 7.90531110763549805f);
    float x2 = x * x;
    float p = fmaf(x2, -2.76076847742355e-16f, 2.00018790482477e-13f);
    p = fmaf(p, x2, -8.60467152213735e-11f);
    p = fmaf(p, x2,  5.12229709037114e-08f);
    p = fmaf(p, x2,  1.48572235717979e-05f);
    p = fmaf(p, x2,  6.37261928875436e-04f);
    p = fmaf(p, x2,  4.89352455891786e-03f);
    p = x * p;
    float q = fmaf(x2, 1.19825839466702e-06f, 1.18534705686654e-04f);
    q = fmaf(q, x2, 2.26843463243900e-03f);
    q = fmaf(q, x2, 4.89352518554385e-03f);        // q in [4.9e-3, 0.91], > 0
    float r = __uint_as_float(0x7EF311C3u - __float_as_uint(q));  // ~5% seed
    r = r * fmaf(-q, r, 2.0f);                     // Newton 1
    r = r * fmaf(-q, r, 2.0f);                     // Newton 2 -> ~1e-5 rel
    return p * r;
}

// ---------------------------------------------------------------------------
// Projection GEMM: C[2048x256] = A[2048x256] @ W[256x256]  (unchanged)
// ---------------------------------------------------------------------------
__global__ __launch_bounds__(256) void proj_kernel(
    const float* __restrict__ Aq, const float* __restrict__ Wq,
    const float* __restrict__ Ak, const float* __restrict__ Wk)
{
    const float* A; const float* W; float* C;
    if (blockIdx.z == 0) { A = Aq; W = Wq; C = g_qh; }
    else                 { A = Ak; W = Wk; C = g_kh; }

    __shared__ float As[16][68];   // [k][m], transposed on store
    __shared__ float Bs[16][68];   // [k][n]

    const int t    = threadIdx.x;
    const int row0 = blockIdx.y * 64;
    const int col0 = blockIdx.x * 64;
    const int ty   = t >> 4;
    const int tx   = t & 15;

    float acc[4][4] = {};

    for (int k0 = 0; k0 < ND; k0 += 16) {
        {
            int r  = t >> 2;
            int c4 = (t & 3) * 4;
            float4 v = *(const float4*)&A[(row0 + r) * ND + k0 + c4];
            As[c4 + 0][r] = v.x;
            As[c4 + 1][r] = v.y;
            As[c4 + 2][r] = v.z;
            As[c4 + 3][r] = v.w;
        }
        {
            int r  = t >> 4;
            int c4 = (t & 15) * 4;
            *(float4*)&Bs[r][c4] = *(const float4*)&W[(k0 + r) * NH + col0 + c4];
        }
        __syncthreads();
        #pragma unroll
        for (int kk = 0; kk < 16; kk++) {
            float4 av = *(float4*)&As[kk][ty * 4];
            float4 bv = *(float4*)&Bs[kk][tx * 4];
            float a_[4] = {av.x, av.y, av.z, av.w};
            float b_[4] = {bv.x, bv.y, bv.z, bv.w};
            #pragma unroll
            for (int i = 0; i < 4; i++)
                #pragma unroll
                for (int j = 0; j < 4; j++)
                    acc[i][j] += a_[i] * b_[j];
        }
        __syncthreads();
    }

    #pragma unroll
    for (int i = 0; i < 4; i++) {
        float4 v = make_float4(acc[i][0], acc[i][1], acc[i][2], acc[i][3]);
        *(float4*)&C[(row0 + ty * 4 + i) * NH + col0 + tx * 4] = v;
    }
}

// ---------------------------------------------------------------------------
// Fused attention — R14 structure; ONLY change: Phase A splits the h-range
// 192 (MUFU tanh) / 64 (FMA-pipe rational tanh) to run both pipes in
// parallel (MUFU.TANH is rt~16; FMA pipe was 7.5% busy).
// ---------------------------------------------------------------------------
__global__ __launch_bounds__(256, 2) void attn_kernel(
    const float* __restrict__ values,
    const float* __restrict__ wv,
    const int*   __restrict__ valid_lens,
    float*       __restrict__ out)
{
    __shared__ float sbuf[32 * STRIDE];    // 33280 B: kh tiles (A) / values tiles + attn (C)
    __shared__ float s_qh[8 * NH];         // 8192 B
    __shared__ float s_wv[NH];             // 1024 B
    float* attn_s = &sbuf[16 * STRIDE];    // 8*512 floats, disjoint from 16-key values tile

    const int t    = threadIdx.x;
    const int w    = t >> 5;
    const int lane = t & 31;
    const int b    = blockIdx.x & 3;               // batch-interleaved
    const int qblk = blockIdx.x >> 2;              // 0..63
    const int qrow = b * NQ + qblk * 8 + w;
    const int vl   = valid_lens[b];                // uniform across block

    // Stage qh rows for this block's 8 queries + wv
    #pragma unroll
    for (int rr = 0; rr < 2; rr++) {
        int i = t + 256 * rr;
        int r = i >> 6;
        int c = (i & 63) * 4;
        *(float4*)&s_qh[r * NH + c] =
            *(const float4*)&g_qh[(b * NQ + qblk * 8 + r) * NH + c];
    }
    if (t < 64) *(float4*)&s_wv[t * 4] = *(const float4*)&wv[t * 4];
    __syncthreads();

    // ---------------- Phase A: scores ----------------
    float sc[16];
    #pragma unroll
    for (int i = 0; i < 16; i++) sc[i] = -1.0e6f;

    const float* khb = &g_kh[(b * NK) * NH];
    const float* myq = &s_qh[w * NH];

    #pragma unroll
    for (int tile = 0; tile < 16; ++tile) {
        if (tile * 32 < vl) {                      // uniform branch
            #pragma unroll
            for (int r = 0; r < 8; ++r) {
                int i  = t + 256 * r;
                int k  = i >> 6;
                int h4 = (i & 63) * 4;
                *(float4*)&sbuf[k * STRIDE + h4] =
                    *(const float4*)&khb[(tile * 32 + k) * NH + h4];
            }
            __syncthreads();

            float accA = 0.f, accB = 0.f;
            const float* myk = &sbuf[lane * STRIDE];
            // h in [0,192): MUFU tanh
            #pragma unroll 4
            for (int h = 0; h < 192; h += 4) {
                float4 kv  = *(const float4*)&myk[h];
                float4 qv  = *(const float4*)&myq[h];
                float4 wv4 = *(const float4*)&s_wv[h];
                accA += wv4.x * tanh_ap(qv.x + kv.x);
                accA += wv4.y * tanh_ap(qv.y + kv.y);
                accA += wv4.z * tanh_ap(qv.z + kv.z);
                accA += wv4.w * tanh_ap(qv.w + kv.w);
            }
            // h in [192,256): FMA-pipe rational tanh (runs concurrently w/ MUFU)
            #pragma unroll 2
            for (int h = 192; h < 256; h += 4) {
                float4 kv  = *(const float4*)&myk[h];
                float4 qv  = *(const float4*)&myq[h];
                float4 wv4 = *(const float4*)&s_wv[h];
                accB += wv4.x * tanh_fma(qv.x + kv.x);
                accB += wv4.y * tanh_fma(qv.y + kv.y);
                accB += wv4.z * tanh_fma(qv.z + kv.z);
                accB += wv4.w * tanh_fma(qv.w + kv.w);
            }
            sc[tile] = accA + accB;                // key = tile*32 + lane
            __syncthreads();
        }
    }

    // mask tail keys
    #pragma unroll
    for (int i = 0; i < 16; i++) {
        int k = i * 32 + lane;
        if (k >= vl) sc[i] = -1.0e6f;
    }

    __syncthreads();   // sbuf reads done before attn_s overlay

    // ---------------- Phase B: softmax ----------------
    float mx = -1.0e30f;
    #pragma unroll
    for (int i = 0; i < 16; i++) mx = fmaxf(mx, sc[i]);
    #pragma unroll
    for (int o = 16; o > 0; o >>= 1)
        mx = fmaxf(mx, __shfl_xor_sync(0xffffffffu, mx, o));

    float sum = 0.f;
    #pragma unroll
    for (int i = 0; i < 16; i++) {
        float e = __expf(sc[i] - mx);
        sum += e;
        attn_s[w * NK + i * 32 + lane] = e;
    }
    #pragma unroll
    for (int o = 16; o > 0; o >>= 1)
        sum += __shfl_xor_sync(0xffffffffu, sum, o);
    const float inv = 1.0f / sum;

    // ---------------- Phase C: out = attn @ values ----------------
    float4 o0 = make_float4(0.f, 0.f, 0.f, 0.f);
    float4 o1 = make_float4(0.f, 0.f, 0.f, 0.f);
    const int nTilesC = (vl + 15) >> 4;
    const float* vb = &values[(b * NK) * ND];

    for (int tile = 0; tile < nTilesC; ++tile) {
        __syncthreads();
        #pragma unroll
        for (int r = 0; r < 4; ++r) {
            int i  = t + 256 * r;
            int k  = i >> 6;
            int h4 = (i & 63) * 4;
            *(float4*)&sbuf[k * STRIDE + h4] =
                *(const float4*)&vb[(tile * 16 + k) * ND + h4];
        }
        __syncthreads();

        #pragma unroll 4
        for (int kk = 0; kk < 16; ++kk) {
            float a = attn_s[w * NK + tile * 16 + kk];
            float4 v0 = *(const float4*)&sbuf[kk * STRIDE + 4 * lane];
            float4 v1 = *(const float4*)&sbuf[kk * STRIDE + 128 + 4 * lane];
            o0.x += a * v0.x; o0.y += a * v0.y; o0.z += a * v0.z; o0.w += a * v0.w;
            o1.x += a * v1.x; o1.y += a * v1.y; o1.z += a * v1.z; o1.w += a * v1.w;
        }
    }

    o0.x *= inv; o0.y *= inv; o0.z *= inv; o0.w *= inv;
    o1.x *= inv; o1.y *= inv; o1.z *= inv; o1.w *= inv;
    *(float4*)&out[qrow * ND + 4 * lane]       = o0;
    *(float4*)&out[qrow * ND + 128 + 4 * lane] = o1;
}

// ---------------------------------------------------------------------------
extern "C" void kernel_launch(void* const* d_in, const int* in_sizes, int n_in,
                              void* d_out, int out_size)
{
    const float* queries = (const float*)d_in[0];
    const float* keys    = (const float*)d_in[1];
    const float* values  = (const float*)d_in[2];
    const float* Wq      = (const float*)d_in[3];
    const float* Wk      = (const float*)d_in[4];
    const float* wv      = (const float*)d_in[5];
    const int*   vlen    = (const int*)d_in[6];
    float* out = (float*)d_out;

    (void)in_sizes; (void)n_in; (void)out_size;

    dim3 pgrid(NH / 64, (NB * NQ) / 64, 2);
    proj_kernel<<<pgrid, 256>>>(queries, Wq, keys, Wk);

    attn_kernel<<<(NB * NQ) / 8, 256>>>(values, wv, vlen, out);
}